// round 14
// baseline (speedup 1.0000x reference)
#include <cuda_runtime.h>
#include <cuda_fp16.h>

#define NB 16
#define SEQ 1024
#define DM 512
#define NH 8
#define HD 64
#define NROWS (NB*SEQ)          // 16384
#define OUT0 (NROWS*DM)         // 8388608 floats: out region, then weights

#define HT_STR 36               // u32 stride for [rows][64-fp16] tiles (32 data + 4 pad)
#define KTH_U  (128*HT_STR)     // one 128x64-fp16 K tile in u32 units

__device__ float    g_q[NROWS*DM];          // fp32 (relu'd) — residual + escore Q source
__device__ unsigned g_qh[NROWS*DM/2];       // fp16x2 of input Q (proj A)
__device__ unsigned g_wh[3*DM*DM/2];        // fp16x2 of Wq/Wk/Wv (proj B)
__device__ unsigned g_kh[NROWS*DM/2];       // fp16x2 projected K (escore B)
__device__ __half   g_vt[(size_t)NB*NH*HD*SEQ];        // V^T fp16 [b,h][n][k] (wv B)
__device__ unsigned g_ws[(size_t)NB*NH*SEQ*(SEQ/2)];   // fp16x2 normalized weights (wv A)
__device__ float    g_att[NROWS*DM];
__device__ int      g_valid[NROWS];

#define SCALE_L2E 0.18033688011112042f   // 0.125 * log2(e)
#define NEGINF __int_as_float(0xff800000)

__device__ __forceinline__ unsigned pk2(float lo, float hi){
    __half2 h = __floats2half2_rn(lo, hi);
    return *(unsigned*)&h;
}
__device__ __forceinline__ float ex2(float x){
    float y; asm("ex2.approx.f32 %0, %1;" : "=f"(y) : "f"(x)); return y;
}
__device__ __forceinline__ void cpasync16(unsigned s, const void* g){
    asm volatile("cp.async.cg.shared.global [%0], [%1], 16;" :: "r"(s), "l"(g));
}
#define CP_COMMIT() asm volatile("cp.async.commit_group;")
#define CP_WAIT(n)  asm volatile("cp.async.wait_group %0;" :: "n"(n))

// fp16 k16: D += A(16x16) * B(16x8), fp32 accum
__device__ __forceinline__ void mma16(float c[4], const unsigned a[4], const unsigned b[2]){
    asm volatile("mma.sync.aligned.m16n8k16.row.col.f32.f16.f16.f32 "
        "{%0,%1,%2,%3}, {%4,%5,%6,%7}, {%8,%9}, {%0,%1,%2,%3};\n"
        : "+f"(c[0]), "+f"(c[1]), "+f"(c[2]), "+f"(c[3])
        : "r"(a[0]), "r"(a[1]), "r"(a[2]), "r"(a[3]), "r"(b[0]), "r"(b[1]));
}

// ---------------------------------------------------------------------------
// prep_q: validity + Q -> fp16 copy. One warp per row.
// ---------------------------------------------------------------------------
__global__ void prep_q(const float* __restrict__ Q){
    int row  = blockIdx.x * 8 + (threadIdx.x >> 5);
    int lane = threadIdx.x & 31;
    const float4* p = (const float4*)(Q + (size_t)row * DM);
    uint2* o = (uint2*)(g_qh + (size_t)row * (DM/2));
    bool nz = false;
    #pragma unroll
    for (int i = 0; i < 4; i++){   // 4 float4 x 32 lanes = 512 = full row ✓
        float4 v = p[lane + i*32];
        nz |= (v.x != 0.f) || (v.y != 0.f) || (v.z != 0.f) || (v.w != 0.f);
        o[lane + i*32] = make_uint2(pk2(v.x, v.y), pk2(v.z, v.w));
    }
    unsigned m = __ballot_sync(0xffffffffu, nz);
    if (lane == 0) g_valid[row] = (m != 0u);
}

// prep_w: W -> fp16. grid (DM*DM/1024, 3), 256 thr, 1 float4/thread.
__global__ void prep_w(const float* __restrict__ Wq,
                       const float* __restrict__ Wk,
                       const float* __restrict__ Wv){
    const int z = blockIdx.y;
    const float* src = (z==0) ? Wq : (z==1) ? Wk : Wv;
    int idx = blockIdx.x * 256 + threadIdx.x;                 // float4 index
    float4 v = ((const float4*)src)[idx];
    ((uint2*)(g_wh + (size_t)z*(DM*DM/2)))[idx] = make_uint2(pk2(v.x,v.y), pk2(v.z,v.w));
}

// ---------------------------------------------------------------------------
// proj: out = relu(Q @ W^T + b), fp16 mma. Block tile 128x128, BK=64 (fp16),
// 3-stage cp.async. 8 warps 4x2, warp tile 32x64.
// Outputs: z=0 q fp32; z=1 k fp16; z=2 V^T fp16 (for wv).
// ---------------------------------------------------------------------------
#define P_STG (128*HT_STR*2)    // A[128x36] + B[128x36] u32 per stage

__global__ __launch_bounds__(256, 2) void proj_kernel(
    const float* __restrict__ bq, const float* __restrict__ bk,
    const float* __restrict__ bv)
{
    extern __shared__ unsigned smem[];
    const int z = blockIdx.z;
    const float* bias = (z==0) ? bq : (z==1) ? bk : bv;
    const unsigned* gA = g_qh;
    const unsigned* gB = g_wh + (size_t)z*(DM*DM/2);

    const int m0 = blockIdx.y * 128, n0 = blockIdx.x * 128;
    const int tid = threadIdx.x, warp = tid >> 5, lane = tid & 31;
    const int wm = warp >> 1, wn = warp & 1;
    const unsigned smb = (unsigned)__cvta_generic_to_shared(smem);

    float acc[2][8][4];
    #pragma unroll
    for (int i=0;i<2;i++)
        #pragma unroll
        for (int j=0;j<8;j++)
            #pragma unroll
            for (int r=0;r<4;r++) acc[i][j][r] = 0.f;

    // stage: A 128 rows x 32 u32 = 1024 chunks (4/thr), B same ✓
    auto issue = [&](int kt, int buf){
        unsigned base = smb + (unsigned)(buf*P_STG)*4u;
        #pragma unroll
        for (int t = 0; t < 4; t++){
            int idx = tid + t*256, r = idx >> 3, c = (idx & 7) * 4;   // u32 col
            cpasync16(base + (unsigned)(r*HT_STR + c)*4u,
                      gA + (size_t)(m0 + r)*(DM/2) + kt*32 + c);
            cpasync16(base + (unsigned)(128*HT_STR + r*HT_STR + c)*4u,
                      gB + (size_t)(n0 + r)*(DM/2) + kt*32 + c);
        }
        CP_COMMIT();
    };

    issue(0, 0); issue(1, 1);

    for (int kt = 0; kt < 8; kt++){           // 8 x 64-fp16 k-tiles
        if (kt < 6) CP_WAIT(1); else CP_WAIT(0);
        __syncthreads();
        if (kt + 2 < 8) issue(kt + 2, (kt + 2) % 3);

        const unsigned* As = smem + (kt % 3)*P_STG;
        const unsigned* Bs = As + 128*HT_STR;
        #pragma unroll
        for (int ks = 0; ks < 32; ks += 8){   // 4 k16 steps (8 u32 each)
            const int cb = ks + (lane & 3);
            unsigned a[2][4];
            #pragma unroll
            for (int mi = 0; mi < 2; mi++){
                int r0 = wm*32 + mi*16 + (lane >> 2);
                a[mi][0] = As[ r0   *HT_STR + cb];
                a[mi][1] = As[(r0+8)*HT_STR + cb];
                a[mi][2] = As[ r0   *HT_STR + cb + 4];
                a[mi][3] = As[(r0+8)*HT_STR + cb + 4];
            }
            #pragma unroll
            for (int ni = 0; ni < 8; ni++){
                int c0 = wn*64 + ni*8 + (lane >> 2);
                unsigned bf[2] = { Bs[c0*HT_STR + cb], Bs[c0*HT_STR + cb + 4] };
                mma16(acc[0][ni], a[0], bf);
                mma16(acc[1][ni], a[1], bf);
            }
        }
        __syncthreads();
    }

    #pragma unroll
    for (int mi = 0; mi < 2; mi++){
        #pragma unroll
        for (int ni = 0; ni < 8; ni++){
            int row = m0 + wm*32 + mi*16 + (lane >> 2);
            int col = n0 + wn*64 + ni*8 + (lane & 3)*2;
            float b0 = __ldg(bias + col), b1 = __ldg(bias + col + 1);
            float v00 = fmaxf(acc[mi][ni][0] + b0, 0.f), v01 = fmaxf(acc[mi][ni][1] + b1, 0.f);
            float v10 = fmaxf(acc[mi][ni][2] + b0, 0.f), v11 = fmaxf(acc[mi][ni][3] + b1, 0.f);
            if (z == 0){
                *(float2*)(g_q + (size_t)row*DM + col)     = make_float2(v00, v01);
                *(float2*)(g_q + (size_t)(row+8)*DM + col) = make_float2(v10, v11);
            } else if (z == 1){   // fp16 K for escore
                g_kh[(size_t)row*(DM/2) + col/2]     = pk2(v00, v01);
                g_kh[(size_t)(row+8)*(DM/2) + col/2] = pk2(v10, v11);
            } else {              // V^T fp16 [b,h][n][k=s] for wv
                int bb2 = row >> 10, s = row & (SEQ-1);
                int hh  = col >> 6,  n = col & 63;
                size_t nb = (size_t)(bb2*NH + hh)*HD;
                g_vt[(nb + n    )*SEQ + s    ] = __float2half_rn(v00);
                g_vt[(nb + n + 1)*SEQ + s    ] = __float2half_rn(v01);
                g_vt[(nb + n    )*SEQ + s + 8] = __float2half_rn(v10);
                g_vt[(nb + n + 1)*SEQ + s + 8] = __float2half_rn(v11);
            }
        }
    }
}

// ---------------------------------------------------------------------------
// escore — no-max softmax via exp2, two streaming passes over K, fp16 mma.
// 128-row K tiles, double-buffered cp.async. Q pre-scaled by 0.125*log2(e);
// weight = ex2(acc + kbias), kbias ∈ {0,-inf}. pass 1 writes fp32 normalized
// weights to wout AND fp16x2 copy to g_ws (wv operand).
// ---------------------------------------------------------------------------
__global__ __launch_bounds__(256, 2) void escore_kernel(float* __restrict__ wout){
    extern __shared__ unsigned smem[];
    unsigned* sQ   = smem;                     // 128*36 u32 (fp16x2)
    unsigned* sK   = sQ + 128*HT_STR;          // 2 * 128*36 u32
    float*    kb   = (float*)(sK + 2*KTH_U);   // 1024: 0 or -inf per k column
    float*    sRS2 = kb + SEQ;                 // 256
    float*    sRS  = sRS2 + 256;               // 128

    const int b = blockIdx.z, h = blockIdx.y;
    const int q0 = blockIdx.x * 128;
    const int tid = threadIdx.x, warp = tid >> 5, lane = tid & 31;
    const int wm = warp >> 1, wn = warp & 1;
    const int rowbase = b * SEQ;

    // Q tile: 128x64 fp32 -> scaled fp16. 2048 float4 = 8 x 256 ✓
    #pragma unroll
    for (int t = 0; t < 8; t++){
        int idx = tid + t*256, r = idx >> 4, c = (idx & 15) * 4;   // fp16 col
        float4 v = *(const float4*)(g_q + (size_t)(rowbase + q0 + r)*DM + h*HD + c);
        *(uint2*)&sQ[r*HT_STR + c/2] = make_uint2(
            pk2(v.x*SCALE_L2E, v.y*SCALE_L2E), pk2(v.z*SCALE_L2E, v.w*SCALE_L2E));
    }
    for (int i = tid; i < SEQ; i += 256)
        kb[i] = g_valid[rowbase + i] ? 0.f : NEGINF;
    __syncthreads();

    const unsigned skb = (unsigned)__cvta_generic_to_shared(sK);
    const unsigned* gK = g_kh + (size_t)rowbase*(DM/2) + h*(HD/2);

    // K tile: 128 rows x 32 u32 = 1024 chunks = 4 x 256 ✓
    auto issueK = [&](int ktile, int buf){
        const unsigned base = skb + (unsigned)(buf*KTH_U)*4u;
        #pragma unroll
        for (int t2 = 0; t2 < 4; t2++){
            int idx = tid + t2*256, r = idx >> 3, c = (idx & 7) * 4;  // u32 col
            cpasync16(base + ((unsigned)(r*HT_STR + c))*4u,
                      gK + (size_t)(ktile*128 + r)*(DM/2) + c);
        }
        CP_COMMIT();
    };

    issueK(0, 0);

    float rsum[4] = {0.f, 0.f, 0.f, 0.f};
    float rs[4]   = {0.f, 0.f, 0.f, 0.f};

    #pragma unroll 1
    for (int pass = 0; pass < 2; pass++){
        #pragma unroll 1
        for (int kt = 0; kt < 8; kt++){
            const int tc = pass*8 + kt;
            const unsigned* sKc = sK + (tc & 1)*KTH_U;
            if (tc < 15){
                issueK((tc + 1) & 7, (tc + 1) & 1);
                CP_WAIT(1);
            } else {
                CP_WAIT(0);
            }
            __syncthreads();

            float acc[2][8][4];
            #pragma unroll
            for (int i=0;i<2;i++)
                #pragma unroll
                for (int j=0;j<8;j++)
                    #pragma unroll
                    for (int r=0;r<4;r++) acc[i][j][r] = 0.f;

            #pragma unroll
            for (int ks = 0; ks < 32; ks += 8){   // 4 k16 steps
                const int cb = ks + (lane & 3);
                unsigned a[2][4];
                #pragma unroll
                for (int mi = 0; mi < 2; mi++){
                    int r0 = wm*32 + mi*16 + (lane >> 2);
                    a[mi][0] = sQ[ r0   *HT_STR + cb];
                    a[mi][1] = sQ[(r0+8)*HT_STR + cb];
                    a[mi][2] = sQ[ r0   *HT_STR + cb + 4];
                    a[mi][3] = sQ[(r0+8)*HT_STR + cb + 4];
                }
                #pragma unroll
                for (int ni = 0; ni < 8; ni++){
                    int c0 = wn*64 + ni*8 + (lane >> 2);
                    unsigned bf[2] = { sKc[c0*HT_STR + cb], sKc[c0*HT_STR + cb + 4] };
                    mma16(acc[0][ni], a[0], bf);
                    mma16(acc[1][ni], a[1], bf);
                }
            }

            // epilogue: e = ex2(acc + kbias); rowsum (pass0) / store (pass1)
            #pragma unroll
            for (int ni = 0; ni < 8; ni++){
                const int cl = kt*128 + wn*64 + ni*8 + (lane & 3)*2;
                const float2 kb2 = *(const float2*)&kb[cl];
                float e0 = ex2(acc[0][ni][0] + kb2.x);
                float e1 = ex2(acc[0][ni][1] + kb2.y);
                float e2 = ex2(acc[0][ni][2] + kb2.x);
                float e3 = ex2(acc[0][ni][3] + kb2.y);
                float e4 = ex2(acc[1][ni][0] + kb2.x);
                float e5 = ex2(acc[1][ni][1] + kb2.y);
                float e6 = ex2(acc[1][ni][2] + kb2.x);
                float e7 = ex2(acc[1][ni][3] + kb2.y);
                if (pass == 0){
                    rsum[0] += e0 + e1;
                    rsum[1] += e2 + e3;
                    rsum[2] += e4 + e5;
                    rsum[3] += e6 + e7;
                } else {
                    float w0 = e0*rs[0], w1 = e1*rs[0];
                    float w2 = e2*rs[1], w3 = e3*rs[1];
                    float w4 = e4*rs[2], w5 = e5*rs[2];
                    float w6 = e6*rs[3], w7 = e7*rs[3];
                    size_t rg = (size_t)((b*NH + h)*SEQ + q0 + wm*32 + (lane>>2));
                    *(float2*)(wout + rg*SEQ + cl)      = make_float2(w0, w1);
                    *(float2*)(wout + (rg+ 8)*SEQ + cl) = make_float2(w2, w3);
                    *(float2*)(wout + (rg+16)*SEQ + cl) = make_float2(w4, w5);
                    *(float2*)(wout + (rg+24)*SEQ + cl) = make_float2(w6, w7);
                    g_ws[ rg     *(SEQ/2) + cl/2] = pk2(w0, w1);
                    g_ws[(rg+ 8) *(SEQ/2) + cl/2] = pk2(w2, w3);
                    g_ws[(rg+16) *(SEQ/2) + cl/2] = pk2(w4, w5);
                    g_ws[(rg+24) *(SEQ/2) + cl/2] = pk2(w6, w7);
                }
            }
            __syncthreads();
        }

        if (pass == 0){
            // quad-reduce (n halves within quad), then combine the 2 n-warps
            #pragma unroll
            for (int j = 0; j < 4; j++){
                rsum[j] += __shfl_xor_sync(0xffffffffu, rsum[j], 1);
                rsum[j] += __shfl_xor_sync(0xffffffffu, rsum[j], 2);
            }
            if ((lane & 3) == 0){
                #pragma unroll
                for (int j = 0; j < 4; j++){
                    int row = wm*32 + j*8 + (lane>>2);
                    sRS2[wn*128 + row] = rsum[j];
                }
            }
            __syncthreads();
            if (tid < 128){
                float s = sRS2[tid] + sRS2[128 + tid];
                bool vq = g_valid[rowbase + q0 + tid] != 0;
                sRS[tid] = (vq && s > 0.f) ? (1.f / s) : 0.f;  // invalid q -> 0
            }
            __syncthreads();
            #pragma unroll
            for (int j = 0; j < 4; j++)
                rs[j] = sRS[wm*32 + j*8 + (lane>>2)];
        }
    }
}

// ---------------------------------------------------------------------------
// wv: attn = W @ V + residual, fp16 mma (mirror of proj pipeline).
// A = g_ws fp16 [m][k=SEQ]; B = g_vt fp16 [n=64][k=SEQ]. 3-stage cp.async,
// k-tile 64 fp16. Block 128x64, 8 warps 4x2, warp tile 32x32.
// ---------------------------------------------------------------------------
#define WV_STG (128*HT_STR + 64*HT_STR)   // A[128x36] + B[64x36] u32 per stage

__global__ __launch_bounds__(256) void wv_kernel(){
    extern __shared__ unsigned smem[];
    const int b = blockIdx.z, h = blockIdx.y;
    const int m0 = blockIdx.x * 128;
    const int tid = threadIdx.x, warp = tid >> 5, lane = tid & 31;
    const int rowbase = b * SEQ;
    const int wm = warp >> 1, wn = warp & 1;
    const unsigned* gA = g_ws + ((size_t)(b*NH + h)*SEQ + m0)*(SEQ/2);
    const unsigned* gB = (const unsigned*)g_vt + (size_t)(b*NH + h)*HD*(SEQ/2);
    const unsigned smb = (unsigned)__cvta_generic_to_shared(smem);

    float acc[2][4][4];
    #pragma unroll
    for (int i=0;i<2;i++)
        #pragma unroll
        for (int j=0;j<4;j++)
            #pragma unroll
            for (int r=0;r<4;r++) acc[i][j][r] = 0.f;

    // stage: A 128x8 chunks = 1024 (4/thr) ✓; B 64x8 = 512 (2/thr) ✓
    auto issue = [&](int kt, int buf){
        unsigned base = smb + (unsigned)(buf*WV_STG)*4u;
        #pragma unroll
        for (int t = 0; t < 4; t++){
            int idx = tid + t*256, r = idx >> 3, c = (idx & 7) * 4;
            cpasync16(base + (unsigned)(r*HT_STR + c)*4u,
                      gA + (size_t)r*(SEQ/2) + kt*32 + c);
        }
        #pragma unroll
        for (int t = 0; t < 2; t++){
            int idx = tid + t*256, r = idx >> 3, c = (idx & 7) * 4;
            cpasync16(base + (unsigned)(128*HT_STR + r*HT_STR + c)*4u,
                      gB + (size_t)r*(SEQ/2) + kt*32 + c);
        }
        CP_COMMIT();
    };

    issue(0, 0); issue(1, 1);

    for (int kt = 0; kt < 16; kt++){          // 16 x 64-fp16 k-tiles
        if (kt < 14) CP_WAIT(1); else CP_WAIT(0);
        __syncthreads();
        if (kt + 2 < 16) issue(kt + 2, (kt + 2) % 3);

        const unsigned* As = smem + (kt % 3)*WV_STG;
        const unsigned* Bs = As + 128*HT_STR;
        #pragma unroll
        for (int ks = 0; ks < 32; ks += 8){   // 4 k16 steps
            const int cb = ks + (lane & 3);
            unsigned a[2][4];
            #pragma unroll
            for (int mi = 0; mi < 2; mi++){
                int r0 = wm*32 + mi*16 + (lane >> 2);
                a[mi][0] = As[ r0   *HT_STR + cb];
                a[mi][1] = As[(r0+8)*HT_STR + cb];
                a[mi][2] = As[ r0   *HT_STR + cb + 4];
                a[mi][3] = As[(r0+8)*HT_STR + cb + 4];
            }
            #pragma unroll
            for (int ni = 0; ni < 4; ni++){
                int c0 = wn*32 + ni*8 + (lane >> 2);
                unsigned bf[2] = { Bs[c0*HT_STR + cb], Bs[c0*HT_STR + cb + 4] };
                mma16(acc[0][ni], a[0], bf);
                mma16(acc[1][ni], a[1], bf);
            }
        }
        __syncthreads();
    }

    #pragma unroll
    for (int mi = 0; mi < 2; mi++){
        #pragma unroll
        for (int ni = 0; ni < 4; ni++){
            int r  = m0 + wm*32 + mi*16 + (lane >> 2);
            int cl = h*HD + wn*32 + ni*8 + (lane & 3)*2;
            size_t base = (size_t)(rowbase + r)*DM + cl;
            float2 q0v = *(const float2*)(g_q + base);
            float2 q1v = *(const float2*)(g_q + base + 8*DM);
            *(float2*)(g_att + base)        = make_float2(acc[mi][ni][0] + q0v.x, acc[mi][ni][1] + q0v.y);
            *(float2*)(g_att + base + 8*DM) = make_float2(acc[mi][ni][2] + q1v.x, acc[mi][ni][3] + q1v.y);
        }
    }
}

// ---------------------------------------------------------------------------
// ln: LayerNorm + relu, one block (128 thr) per row
// ---------------------------------------------------------------------------
__global__ __launch_bounds__(128) void ln_kernel(const float* __restrict__ lnw,
                                                 const float* __restrict__ lnb,
                                                 float* __restrict__ out){
    const int row = blockIdx.x, tid = threadIdx.x;
    const float4 x = *(const float4*)(g_att + (size_t)row*DM + tid*4);
    float s  = x.x + x.y + x.z + x.w;
    float ss = fmaf(x.x, x.x, fmaf(x.y, x.y, fmaf(x.z, x.z, x.w*x.w)));
    #pragma unroll
    for (int o = 16; o > 0; o >>= 1){
        s  += __shfl_xor_sync(0xffffffffu, s,  o);
        ss += __shfl_xor_sync(0xffffffffu, ss, o);
    }
    __shared__ float red[8];
    int warp = tid >> 5, lane = tid & 31;
    if (lane == 0){ red[warp] = s; red[warp+4] = ss; }
    __syncthreads();
    s  = red[0] + red[1] + red[2] + red[3];
    ss = red[4] + red[5] + red[6] + red[7];
    float mu  = s * (1.0f/DM);
    float inv = rsqrtf(ss * (1.0f/DM) - mu*mu + 1e-5f);
    const float4 w = *(const float4*)(lnw + tid*4);
    const float4 bb = *(const float4*)(lnb + tid*4);
    float4 y;
    y.x = fmaxf((x.x - mu)*inv*w.x + bb.x, 0.f);
    y.y = fmaxf((x.y - mu)*inv*w.y + bb.y, 0.f);
    y.z = fmaxf((x.z - mu)*inv*w.z + bb.z, 0.f);
    y.w = fmaxf((x.w - mu)*inv*w.w + bb.w, 0.f);
    *(float4*)(out + (size_t)row*DM + tid*4) = y;
}

// ---------------------------------------------------------------------------
extern "C" void kernel_launch(void* const* d_in, const int* in_sizes, int n_in,
                              void* d_out, int out_size){
    const float* Q   = (const float*)d_in[0];
    const float* Wq  = (const float*)d_in[1];
    const float* bq  = (const float*)d_in[2];
    const float* Wk  = (const float*)d_in[3];
    const float* bk  = (const float*)d_in[4];
    const float* Wv  = (const float*)d_in[5];
    const float* bv  = (const float*)d_in[6];
    const float* lnw = (const float*)d_in[7];
    const float* lnb = (const float*)d_in[8];
    float* out = (float*)d_out;

    prep_q<<<NROWS/8, 256>>>(Q);
    prep_w<<<dim3(DM*DM/1024, 3), 256>>>(Wq, Wk, Wv);

    const int pj_smem = 3 * P_STG * 4;   // 110592
    cudaFuncSetAttribute(proj_kernel, cudaFuncAttributeMaxDynamicSharedMemorySize, pj_smem);
    proj_kernel<<<dim3(DM/128, NROWS/128, 3), 256, pj_smem>>>(bq, bk, bv);

    // escore smem: 3*128*36 u32 + 1024 kb + 384 red = 60928 B
    const int es_smem = (3*128*HT_STR)*4 + SEQ*4 + 384*4;
    cudaFuncSetAttribute(escore_kernel, cudaFuncAttributeMaxDynamicSharedMemorySize, es_smem);
    escore_kernel<<<dim3(SEQ/128, NH, NB), 256, es_smem>>>(out + OUT0);

    const int wv_smem = 3 * WV_STG * 4;  // 82944
    cudaFuncSetAttribute(wv_kernel, cudaFuncAttributeMaxDynamicSharedMemorySize, wv_smem);
    wv_kernel<<<dim3(SEQ/128, NH, NB), 256, wv_smem>>>();

    ln_kernel<<<NROWS, 128>>>(lnw, lnb, out);
}

// round 15
// speedup vs baseline: 1.1984x; 1.1984x over previous
#include <cuda_runtime.h>
#include <cuda_fp16.h>

#define NB 16
#define SEQ 1024
#define DM 512
#define NH 8
#define HD 64
#define NROWS (NB*SEQ)          // 16384
#define OUT0 (NROWS*DM)         // 8388608 floats: out region, then weights

#define HT_STR 36               // u32 stride for [rows][64-fp16] tiles (32 data + 4 pad)
#define VT_STR 68               // u32 stride for V^T [n][128-fp16] tiles (64 data + 4 pad)
#define KTH_U  (128*HT_STR)     // one 128x64-fp16 K tile in u32 units
#define VTT_U  (64*VT_STR)      // one 64x128-fp16 V^T tile in u32 units
#define RED_STR 72              // fp32 stride for acc_o reduction region

__device__ float    g_q[NROWS*DM];          // fp32 (relu'd) — residual + escore Q source
__device__ unsigned g_qh[NROWS*DM/2];       // fp16x2 of input Q (proj A)
__device__ unsigned g_wh[3*DM*DM/2];        // fp16x2 of Wq/Wk/Wv (proj B)
__device__ unsigned g_kh[NROWS*DM/2];       // fp16x2 projected K (escore B)
__device__ __half   g_vt[(size_t)NB*NH*HD*SEQ];   // V^T fp16 [b,h][n][k=s]
__device__ float    g_att[NROWS*DM];
__device__ int      g_valid[NROWS];

#define SCALE_L2E 0.18033688011112042f   // 0.125 * log2(e)
#define NEGINF __int_as_float(0xff800000)

__device__ __forceinline__ unsigned pk2(float lo, float hi){
    __half2 h = __floats2half2_rn(lo, hi);
    return *(unsigned*)&h;
}
__device__ __forceinline__ float ex2(float x){
    float y; asm("ex2.approx.f32 %0, %1;" : "=f"(y) : "f"(x)); return y;
}
__device__ __forceinline__ void cpasync16(unsigned s, const void* g){
    asm volatile("cp.async.cg.shared.global [%0], [%1], 16;" :: "r"(s), "l"(g));
}
#define CP_COMMIT() asm volatile("cp.async.commit_group;")
#define CP_WAIT(n)  asm volatile("cp.async.wait_group %0;" :: "n"(n))

// fp16 k16: D += A(16x16) * B(16x8), fp32 accum
__device__ __forceinline__ void mma16(float c[4], const unsigned a[4], const unsigned b[2]){
    asm volatile("mma.sync.aligned.m16n8k16.row.col.f32.f16.f16.f32 "
        "{%0,%1,%2,%3}, {%4,%5,%6,%7}, {%8,%9}, {%0,%1,%2,%3};\n"
        : "+f"(c[0]), "+f"(c[1]), "+f"(c[2]), "+f"(c[3])
        : "r"(a[0]), "r"(a[1]), "r"(a[2]), "r"(a[3]), "r"(b[0]), "r"(b[1]));
}

// ---------------------------------------------------------------------------
// prep_q: validity + Q -> fp16. One warp per row.
// ---------------------------------------------------------------------------
__global__ void prep_q(const float* __restrict__ Q){
    int row  = blockIdx.x * 8 + (threadIdx.x >> 5);
    int lane = threadIdx.x & 31;
    const float4* p = (const float4*)(Q + (size_t)row * DM);
    uint2* o = (uint2*)(g_qh + (size_t)row * (DM/2));
    bool nz = false;
    #pragma unroll
    for (int i = 0; i < 4; i++){   // 4 float4 x 32 lanes = full row ✓
        float4 v = p[lane + i*32];
        nz |= (v.x != 0.f) || (v.y != 0.f) || (v.z != 0.f) || (v.w != 0.f);
        o[lane + i*32] = make_uint2(pk2(v.x, v.y), pk2(v.z, v.w));
    }
    unsigned m = __ballot_sync(0xffffffffu, nz);
    if (lane == 0) g_valid[row] = (m != 0u);
}

// prep_w: W -> fp16. grid (DM*DM/1024, 3), 256 thr, 1 float4/thread.
__global__ void prep_w(const float* __restrict__ Wq,
                       const float* __restrict__ Wk,
                       const float* __restrict__ Wv){
    const int z = blockIdx.y;
    const float* src = (z==0) ? Wq : (z==1) ? Wk : Wv;
    int idx = blockIdx.x * 256 + threadIdx.x;
    float4 v = ((const float4*)src)[idx];
    ((uint2*)(g_wh + (size_t)z*(DM*DM/2)))[idx] = make_uint2(pk2(v.x,v.y), pk2(v.z,v.w));
}

// ---------------------------------------------------------------------------
// proj: out = relu(Q @ W^T + b), fp16 mma. Block 128x128, BK=64, 3-stage.
// Outputs: z=0 q fp32; z=1 k fp16; z=2 V^T fp16.  (R14-proven)
// ---------------------------------------------------------------------------
#define P_STG (128*HT_STR*2)

__global__ __launch_bounds__(256, 2) void proj_kernel(
    const float* __restrict__ bq, const float* __restrict__ bk,
    const float* __restrict__ bv)
{
    extern __shared__ unsigned smem[];
    const int z = blockIdx.z;
    const float* bias = (z==0) ? bq : (z==1) ? bk : bv;
    const unsigned* gA = g_qh;
    const unsigned* gB = g_wh + (size_t)z*(DM*DM/2);

    const int m0 = blockIdx.y * 128, n0 = blockIdx.x * 128;
    const int tid = threadIdx.x, warp = tid >> 5, lane = tid & 31;
    const int wm = warp >> 1, wn = warp & 1;
    const unsigned smb = (unsigned)__cvta_generic_to_shared(smem);

    float acc[2][8][4];
    #pragma unroll
    for (int i=0;i<2;i++)
        #pragma unroll
        for (int j=0;j<8;j++)
            #pragma unroll
            for (int r=0;r<4;r++) acc[i][j][r] = 0.f;

    auto issue = [&](int kt, int buf){
        unsigned base = smb + (unsigned)(buf*P_STG)*4u;
        #pragma unroll
        for (int t = 0; t < 4; t++){
            int idx = tid + t*256, r = idx >> 3, c = (idx & 7) * 4;
            cpasync16(base + (unsigned)(r*HT_STR + c)*4u,
                      gA + (size_t)(m0 + r)*(DM/2) + kt*32 + c);
            cpasync16(base + (unsigned)(128*HT_STR + r*HT_STR + c)*4u,
                      gB + (size_t)(n0 + r)*(DM/2) + kt*32 + c);
        }
        CP_COMMIT();
    };

    issue(0, 0); issue(1, 1);

    for (int kt = 0; kt < 8; kt++){
        if (kt < 6) CP_WAIT(1); else CP_WAIT(0);
        __syncthreads();
        if (kt + 2 < 8) issue(kt + 2, (kt + 2) % 3);

        const unsigned* As = smem + (kt % 3)*P_STG;
        const unsigned* Bs = As + 128*HT_STR;
        #pragma unroll
        for (int ks = 0; ks < 32; ks += 8){
            const int cb = ks + (lane & 3);
            unsigned a[2][4];
            #pragma unroll
            for (int mi = 0; mi < 2; mi++){
                int r0 = wm*32 + mi*16 + (lane >> 2);
                a[mi][0] = As[ r0   *HT_STR + cb];
                a[mi][1] = As[(r0+8)*HT_STR + cb];
                a[mi][2] = As[ r0   *HT_STR + cb + 4];
                a[mi][3] = As[(r0+8)*HT_STR + cb + 4];
            }
            #pragma unroll
            for (int ni = 0; ni < 8; ni++){
                int c0 = wn*64 + ni*8 + (lane >> 2);
                unsigned bf[2] = { Bs[c0*HT_STR + cb], Bs[c0*HT_STR + cb + 4] };
                mma16(acc[0][ni], a[0], bf);
                mma16(acc[1][ni], a[1], bf);
            }
        }
        __syncthreads();
    }

    #pragma unroll
    for (int mi = 0; mi < 2; mi++){
        #pragma unroll
        for (int ni = 0; ni < 8; ni++){
            int row = m0 + wm*32 + mi*16 + (lane >> 2);
            int col = n0 + wn*64 + ni*8 + (lane & 3)*2;
            float b0 = __ldg(bias + col), b1 = __ldg(bias + col + 1);
            float v00 = fmaxf(acc[mi][ni][0] + b0, 0.f), v01 = fmaxf(acc[mi][ni][1] + b1, 0.f);
            float v10 = fmaxf(acc[mi][ni][2] + b0, 0.f), v11 = fmaxf(acc[mi][ni][3] + b1, 0.f);
            if (z == 0){
                *(float2*)(g_q + (size_t)row*DM + col)     = make_float2(v00, v01);
                *(float2*)(g_q + (size_t)(row+8)*DM + col) = make_float2(v10, v11);
            } else if (z == 1){
                g_kh[(size_t)row*(DM/2) + col/2]     = pk2(v00, v01);
                g_kh[(size_t)(row+8)*(DM/2) + col/2] = pk2(v10, v11);
            } else {              // V^T fp16 [b,h][n][k=s]
                int bb2 = row >> 10, s = row & (SEQ-1);
                int hh  = col >> 6,  n = col & 63;
                size_t nb = (size_t)(bb2*NH + hh)*HD;
                g_vt[(nb + n    )*SEQ + s    ] = __float2half_rn(v00);
                g_vt[(nb + n + 1)*SEQ + s    ] = __float2half_rn(v01);
                g_vt[(nb + n    )*SEQ + s + 8] = __float2half_rn(v10);
                g_vt[(nb + n + 1)*SEQ + s + 8] = __float2half_rn(v11);
            }
        }
    }
}

// ---------------------------------------------------------------------------
// fused attention: scores + no-max softmax + weights write + P@V + residual.
// 512 threads, 16 warps as 4(wm) x 4(wn). Per (b, h, 128-row q-tile).
// pass 0: score mma -> ex2 -> rowsums.   pass 1: recompute, write fp32
// weights to wout, pack C-frags into fp16 A-frags (FA trick), acc_o += P@V^T.
// K tiles 128x64 fp16, V^T tiles 64x128 fp16, double-buffered cp.async.
// ---------------------------------------------------------------------------
__global__ __launch_bounds__(512) void fused_attn(float* __restrict__ wout){
    extern __shared__ unsigned smem[];
    unsigned* sQ   = smem;                      // 128*36
    unsigned* sK   = sQ + 128*HT_STR;           // 2 * 128*36
    unsigned* sVT  = sK + 2*KTH_U;              // 2 * 64*68
    float*    kb   = (float*)(sVT + 2*VTT_U);   // 1024
    float*    sRS2 = kb + SEQ;                  // 4*128
    float*    sRS  = sRS2 + 512;                // 128
    float*    red  = (float*)sK;                // reuse: 128*72 fp32 (fits in sK)

    const int b = blockIdx.z, h = blockIdx.y;
    const int q0 = blockIdx.x * 128;
    const int tid = threadIdx.x, warp = tid >> 5, lane = tid & 31;
    const int wm = warp >> 2, wn = warp & 3;
    const int rowbase = b * SEQ;

    // Q tile: 128x64 fp32 -> scaled fp16. 2048 float4 = 4 x 512 ✓
    #pragma unroll
    for (int t = 0; t < 4; t++){
        int idx = tid + t*512, r = idx >> 4, c = (idx & 15) * 4;
        float4 v = *(const float4*)(g_q + (size_t)(rowbase + q0 + r)*DM + h*HD + c);
        *(uint2*)&sQ[r*HT_STR + c/2] = make_uint2(
            pk2(v.x*SCALE_L2E, v.y*SCALE_L2E), pk2(v.z*SCALE_L2E, v.w*SCALE_L2E));
    }
    for (int i = tid; i < SEQ; i += 512)
        kb[i] = g_valid[rowbase + i] ? 0.f : NEGINF;
    __syncthreads();

    const unsigned skb = (unsigned)__cvta_generic_to_shared(sK);
    const unsigned svb = (unsigned)__cvta_generic_to_shared(sVT);
    const unsigned* gK  = g_kh + (size_t)rowbase*(DM/2) + h*(HD/2);
    const unsigned* gVT = (const unsigned*)g_vt + (size_t)(b*NH + h)*HD*(SEQ/2);

    // K tile: 128 rows x 32 u32 = 1024 chunks = 2 x 512 ✓
    auto issueK = [&](int ktile, int buf){
        const unsigned base = skb + (unsigned)(buf*KTH_U)*4u;
        #pragma unroll
        for (int t = 0; t < 2; t++){
            int idx = tid + t*512, r = idx >> 3, c = (idx & 7) * 4;
            cpasync16(base + ((unsigned)(r*HT_STR + c))*4u,
                      gK + (size_t)(ktile*128 + r)*(DM/2) + c);
        }
    };
    // V^T tile: 64 rows x 64 u32 = 1024 chunks = 2 x 512 ✓
    auto issueV = [&](int ktile, int buf){
        const unsigned base = svb + (unsigned)(buf*VTT_U)*4u;
        #pragma unroll
        for (int t = 0; t < 2; t++){
            int idx = tid + t*512, r = idx >> 4, c = (idx & 15) * 4;
            cpasync16(base + ((unsigned)(r*VT_STR + c))*4u,
                      gVT + (size_t)r*(SEQ/2) + ktile*64 + c);
        }
    };

    issueK(0, 0); CP_COMMIT();

    float rsum[4] = {0.f, 0.f, 0.f, 0.f};
    float rs[4];

    // ---- pass 0: rowsums ----
    #pragma unroll 1
    for (int kt = 0; kt < 8; kt++){
        if (kt < 7){ issueK(kt + 1, (kt + 1) & 1); CP_COMMIT(); CP_WAIT(1); }
        else CP_WAIT(0);
        __syncthreads();

        const unsigned* sKc = sK + (kt & 1)*KTH_U;
        float acc[2][4][4];
        #pragma unroll
        for (int i=0;i<2;i++)
            #pragma unroll
            for (int j=0;j<4;j++)
                #pragma unroll
                for (int r=0;r<4;r++) acc[i][j][r] = 0.f;

        #pragma unroll
        for (int ks = 0; ks < 32; ks += 8){
            const int cb = ks + (lane & 3);
            unsigned a[2][4];
            #pragma unroll
            for (int mi = 0; mi < 2; mi++){
                int r0 = wm*32 + mi*16 + (lane >> 2);
                a[mi][0] = sQ[ r0   *HT_STR + cb];
                a[mi][1] = sQ[(r0+8)*HT_STR + cb];
                a[mi][2] = sQ[ r0   *HT_STR + cb + 4];
                a[mi][3] = sQ[(r0+8)*HT_STR + cb + 4];
            }
            #pragma unroll
            for (int ni = 0; ni < 4; ni++){
                int c0 = wn*32 + ni*8 + (lane >> 2);
                unsigned bf[2] = { sKc[c0*HT_STR + cb], sKc[c0*HT_STR + cb + 4] };
                mma16(acc[0][ni], a[0], bf);
                mma16(acc[1][ni], a[1], bf);
            }
        }
        #pragma unroll
        for (int ni = 0; ni < 4; ni++){
            const int cl = kt*128 + wn*32 + ni*8 + (lane & 3)*2;
            const float2 kb2 = *(const float2*)&kb[cl];
            rsum[0] += ex2(acc[0][ni][0] + kb2.x) + ex2(acc[0][ni][1] + kb2.y);
            rsum[1] += ex2(acc[0][ni][2] + kb2.x) + ex2(acc[0][ni][3] + kb2.y);
            rsum[2] += ex2(acc[1][ni][0] + kb2.x) + ex2(acc[1][ni][1] + kb2.y);
            rsum[3] += ex2(acc[1][ni][2] + kb2.x) + ex2(acc[1][ni][3] + kb2.y);
        }
        __syncthreads();
    }

    // prefetch pass-1 tile 0 (K + V) — overlaps the rs reduction
    issueK(0, 0); issueV(0, 0); CP_COMMIT();

    // reduce rowsums: quad shfl (covers warp's 32 n-cols), then 4 wn warps
    #pragma unroll
    for (int j = 0; j < 4; j++){
        rsum[j] += __shfl_xor_sync(0xffffffffu, rsum[j], 1);
        rsum[j] += __shfl_xor_sync(0xffffffffu, rsum[j], 2);
    }
    if ((lane & 3) == 0){
        #pragma unroll
        for (int j = 0; j < 4; j++){
            int row = wm*32 + (j>>1)*16 + (j&1)*8 + (lane>>2);
            sRS2[wn*128 + row] = rsum[j];
        }
    }
    __syncthreads();
    if (tid < 128){
        float s = sRS2[tid] + sRS2[128+tid] + sRS2[256+tid] + sRS2[384+tid];
        bool vq = g_valid[rowbase + q0 + tid] != 0;
        sRS[tid] = (vq && s > 0.f) ? (1.f / s) : 0.f;   // invalid q -> 0
    }
    __syncthreads();
    #pragma unroll
    for (int j = 0; j < 4; j++)
        rs[j] = sRS[wm*32 + (j>>1)*16 + (j&1)*8 + (lane>>2)];

    // ---- pass 1: weights + P@V ----
    float acco[2][8][4];
    #pragma unroll
    for (int i=0;i<2;i++)
        #pragma unroll
        for (int j=0;j<8;j++)
            #pragma unroll
            for (int r=0;r<4;r++) acco[i][j][r] = 0.f;

    #pragma unroll 1
    for (int kt = 0; kt < 8; kt++){
        if (kt < 7){ issueK(kt + 1, (kt + 1) & 1); issueV(kt + 1, (kt + 1) & 1);
                     CP_COMMIT(); CP_WAIT(1); }
        else CP_WAIT(0);
        __syncthreads();

        const unsigned* sKc = sK  + (kt & 1)*KTH_U;
        const unsigned* sVc = sVT + (kt & 1)*VTT_U;

        float acc[2][4][4];
        #pragma unroll
        for (int i=0;i<2;i++)
            #pragma unroll
            for (int j=0;j<4;j++)
                #pragma unroll
                for (int r=0;r<4;r++) acc[i][j][r] = 0.f;

        #pragma unroll
        for (int ks = 0; ks < 32; ks += 8){
            const int cb = ks + (lane & 3);
            unsigned a[2][4];
            #pragma unroll
            for (int mi = 0; mi < 2; mi++){
                int r0 = wm*32 + mi*16 + (lane >> 2);
                a[mi][0] = sQ[ r0   *HT_STR + cb];
                a[mi][1] = sQ[(r0+8)*HT_STR + cb];
                a[mi][2] = sQ[ r0   *HT_STR + cb + 4];
                a[mi][3] = sQ[(r0+8)*HT_STR + cb + 4];
            }
            #pragma unroll
            for (int ni = 0; ni < 4; ni++){
                int c0 = wn*32 + ni*8 + (lane >> 2);
                unsigned bf[2] = { sKc[c0*HT_STR + cb], sKc[c0*HT_STR + cb + 4] };
                mma16(acc[0][ni], a[0], bf);
                mma16(acc[1][ni], a[1], bf);
            }
        }

        // epilogue: normalize, store fp32 weights, pack P A-frags (FA trick)
        unsigned AF[2][2][4];   // [mi][ksub][4]
        #pragma unroll
        for (int ni = 0; ni < 4; ni++){
            const int cl = kt*128 + wn*32 + ni*8 + (lane & 3)*2;
            const float2 kb2 = *(const float2*)&kb[cl];
            float w0 = ex2(acc[0][ni][0] + kb2.x)*rs[0];
            float w1 = ex2(acc[0][ni][1] + kb2.y)*rs[0];
            float w2 = ex2(acc[0][ni][2] + kb2.x)*rs[1];
            float w3 = ex2(acc[0][ni][3] + kb2.y)*rs[1];
            float w4 = ex2(acc[1][ni][0] + kb2.x)*rs[2];
            float w5 = ex2(acc[1][ni][1] + kb2.y)*rs[2];
            float w6 = ex2(acc[1][ni][2] + kb2.x)*rs[3];
            float w7 = ex2(acc[1][ni][3] + kb2.y)*rs[3];
            size_t rg = (size_t)((b*NH + h)*SEQ + q0 + wm*32 + (lane>>2));
            *(float2*)(wout + rg*SEQ + cl)      = make_float2(w0, w1);
            *(float2*)(wout + (rg+ 8)*SEQ + cl) = make_float2(w2, w3);
            *(float2*)(wout + (rg+16)*SEQ + cl) = make_float2(w4, w5);
            *(float2*)(wout + (rg+24)*SEQ + cl) = make_float2(w6, w7);
            // C-frag -> A-frag: ni pair (2ksub, 2ksub+1) forms one k16 frag
            AF[0][ni>>1][(ni&1)*2    ] = pk2(w0, w1);
            AF[0][ni>>1][(ni&1)*2 + 1] = pk2(w2, w3);
            AF[1][ni>>1][(ni&1)*2    ] = pk2(w4, w5);
            AF[1][ni>>1][(ni&1)*2 + 1] = pk2(w6, w7);
        }

        // acc_o += P @ V^T  (warp k-slice: fp16 k = kt*128 + wn*32 + ksub*16)
        #pragma unroll
        for (int ksub = 0; ksub < 2; ksub++){
            const int cb = wn*16 + ksub*8 + (lane & 3);
            #pragma unroll
            for (int nj = 0; nj < 8; nj++){
                int c0 = nj*8 + (lane >> 2);
                unsigned bf[2] = { sVc[c0*VT_STR + cb], sVc[c0*VT_STR + cb + 4] };
                mma16(acco[0][nj], AF[0][ksub], bf);
                mma16(acco[1][nj], AF[1][ksub], bf);
            }
        }
        __syncthreads();
    }

    // ---- cross-warp acc_o reduction over wn (sequential into red) ----
    #pragma unroll 1
    for (int s = 0; s < 4; s++){
        if (wn == s){
            #pragma unroll
            for (int mi = 0; mi < 2; mi++){
                #pragma unroll
                for (int nj = 0; nj < 8; nj++){
                    int r = wm*32 + mi*16 + (lane >> 2);
                    int c = nj*8 + (lane & 3)*2;
                    if (s == 0){
                        *(float2*)&red[ r   *RED_STR + c] = make_float2(acco[mi][nj][0], acco[mi][nj][1]);
                        *(float2*)&red[(r+8)*RED_STR + c] = make_float2(acco[mi][nj][2], acco[mi][nj][3]);
                    } else {
                        float2 x0 = *(float2*)&red[ r   *RED_STR + c];
                        float2 x1 = *(float2*)&red[(r+8)*RED_STR + c];
                        *(float2*)&red[ r   *RED_STR + c] = make_float2(x0.x + acco[mi][nj][0], x0.y + acco[mi][nj][1]);
                        *(float2*)&red[(r+8)*RED_STR + c] = make_float2(x1.x + acco[mi][nj][2], x1.y + acco[mi][nj][3]);
                    }
                }
            }
        }
        __syncthreads();
    }

    // output + residual: 128x64 = 2048 float4 = 4 x 512 ✓
    #pragma unroll
    for (int t = 0; t < 4; t++){
        int idx = tid + t*512, r = idx >> 4, c = (idx & 15) * 4;
        float4 s4 = *(const float4*)&red[r*RED_STR + c];
        size_t base = (size_t)(rowbase + q0 + r)*DM + h*HD + c;
        float4 q4 = *(const float4*)(g_q + base);
        *(float4*)(g_att + base) = make_float4(s4.x+q4.x, s4.y+q4.y, s4.z+q4.z, s4.w+q4.w);
    }
}

// ---------------------------------------------------------------------------
// ln: LayerNorm + relu, one block (128 thr) per row
// ---------------------------------------------------------------------------
__global__ __launch_bounds__(128) void ln_kernel(const float* __restrict__ lnw,
                                                 const float* __restrict__ lnb,
                                                 float* __restrict__ out){
    const int row = blockIdx.x, tid = threadIdx.x;
    const float4 x = *(const float4*)(g_att + (size_t)row*DM + tid*4);
    float s  = x.x + x.y + x.z + x.w;
    float ss = fmaf(x.x, x.x, fmaf(x.y, x.y, fmaf(x.z, x.z, x.w*x.w)));
    #pragma unroll
    for (int o = 16; o > 0; o >>= 1){
        s  += __shfl_xor_sync(0xffffffffu, s,  o);
        ss += __shfl_xor_sync(0xffffffffu, ss, o);
    }
    __shared__ float red[8];
    int warp = tid >> 5, lane = tid & 31;
    if (lane == 0){ red[warp] = s; red[warp+4] = ss; }
    __syncthreads();
    s  = red[0] + red[1] + red[2] + red[3];
    ss = red[4] + red[5] + red[6] + red[7];
    float mu  = s * (1.0f/DM);
    float inv = rsqrtf(ss * (1.0f/DM) - mu*mu + 1e-5f);
    const float4 w = *(const float4*)(lnw + tid*4);
    const float4 bb = *(const float4*)(lnb + tid*4);
    float4 y;
    y.x = fmaxf((x.x - mu)*inv*w.x + bb.x, 0.f);
    y.y = fmaxf((x.y - mu)*inv*w.y + bb.y, 0.f);
    y.z = fmaxf((x.z - mu)*inv*w.z + bb.z, 0.f);
    y.w = fmaxf((x.w - mu)*inv*w.w + bb.w, 0.f);
    *(float4*)(out + (size_t)row*DM + tid*4) = y;
}

// ---------------------------------------------------------------------------
extern "C" void kernel_launch(void* const* d_in, const int* in_sizes, int n_in,
                              void* d_out, int out_size){
    const float* Q   = (const float*)d_in[0];
    const float* Wq  = (const float*)d_in[1];
    const float* bq  = (const float*)d_in[2];
    const float* Wk  = (const float*)d_in[3];
    const float* bk  = (const float*)d_in[4];
    const float* Wv  = (const float*)d_in[5];
    const float* bv  = (const float*)d_in[6];
    const float* lnw = (const float*)d_in[7];
    const float* lnb = (const float*)d_in[8];
    float* out = (float*)d_out;

    prep_q<<<NROWS/8, 256>>>(Q);
    prep_w<<<dim3(DM*DM/1024, 3), 256>>>(Wq, Wk, Wv);

    const int pj_smem = 3 * P_STG * 4;   // 110592
    cudaFuncSetAttribute(proj_kernel, cudaFuncAttributeMaxDynamicSharedMemorySize, pj_smem);
    proj_kernel<<<dim3(DM/128, NROWS/128, 3), 256, pj_smem>>>(bq, bk, bv);

    // fused smem: 128*36 + 2*128*36 + 2*64*68 u32 + (1024 + 512 + 128) fp32
    const int fa_smem = (128*HT_STR + 2*KTH_U + 2*VTT_U)*4 + (SEQ + 512 + 128)*4;  // 96768
    cudaFuncSetAttribute(fused_attn, cudaFuncAttributeMaxDynamicSharedMemorySize, fa_smem);
    fused_attn<<<dim3(SEQ/128, NH, NB), 512, fa_smem>>>(out + OUT0);

    ln_kernel<<<NROWS, 128>>>(lnw, lnb, out);
}

// round 16
// speedup vs baseline: 1.2325x; 1.0285x over previous
#include <cuda_runtime.h>
#include <cuda_fp16.h>

#define NB 16
#define SEQ 1024
#define DM 512
#define NH 8
#define HD 64
#define NROWS (NB*SEQ)          // 16384
#define OUT0 (NROWS*DM)         // 8388608 floats: out region, then weights

#define HT_STR 36               // u32 stride for [rows][64-fp16] tiles (32 data + 4 pad)
#define VT_STR 68               // u32 stride for V^T [n][128-fp16] tiles (64 data + 4 pad)
#define KTH_U  (128*HT_STR)     // one 128x64-fp16 K tile in u32 units
#define VTT_U  (64*VT_STR)      // one 64x128-fp16 V^T tile in u32 units
#define RED_STR 72              // fp32 stride for acc_o reduction region

__device__ float    g_q[NROWS*DM];          // fp32 (relu'd) — residual + attn Q source
__device__ unsigned g_qh[NROWS*DM/2];       // fp16x2 of input Q (proj A)
__device__ unsigned g_wh[3*DM*DM/2];        // fp16x2 of Wq/Wk/Wv (proj B)
__device__ unsigned g_kh[NROWS*DM/2];       // fp16x2 projected K
__device__ __half   g_vt[(size_t)NB*NH*HD*SEQ];   // V^T fp16 [b,h][n][k=s]
__device__ float    g_att[NROWS*DM];
__device__ int      g_valid[NROWS];

#define SCALE_L2E 0.18033688011112042f   // 0.125 * log2(e)
#define NEGINF __int_as_float(0xff800000)

__device__ __forceinline__ unsigned pk2(float lo, float hi){
    __half2 h = __floats2half2_rn(lo, hi);
    return *(unsigned*)&h;
}
__device__ __forceinline__ float ex2(float x){
    float y; asm("ex2.approx.f32 %0, %1;" : "=f"(y) : "f"(x)); return y;
}
__device__ __forceinline__ void cpasync16(unsigned s, const void* g){
    asm volatile("cp.async.cg.shared.global [%0], [%1], 16;" :: "r"(s), "l"(g));
}
#define CP_COMMIT() asm volatile("cp.async.commit_group;")
#define CP_WAIT(n)  asm volatile("cp.async.wait_group %0;" :: "n"(n))

// fp16 k16: D += A(16x16) * B(16x8), fp32 accum
__device__ __forceinline__ void mma16(float c[4], const unsigned a[4], const unsigned b[2]){
    asm volatile("mma.sync.aligned.m16n8k16.row.col.f32.f16.f16.f32 "
        "{%0,%1,%2,%3}, {%4,%5,%6,%7}, {%8,%9}, {%0,%1,%2,%3};\n"
        : "+f"(c[0]), "+f"(c[1]), "+f"(c[2]), "+f"(c[3])
        : "r"(a[0]), "r"(a[1]), "r"(a[2]), "r"(a[3]), "r"(b[0]), "r"(b[1]));
}

// ---------------------------------------------------------------------------
// prep_q: validity + Q -> fp16. One warp per row.
// ---------------------------------------------------------------------------
__global__ void prep_q(const float* __restrict__ Q){
    int row  = blockIdx.x * 8 + (threadIdx.x >> 5);
    int lane = threadIdx.x & 31;
    const float4* p = (const float4*)(Q + (size_t)row * DM);
    uint2* o = (uint2*)(g_qh + (size_t)row * (DM/2));
    bool nz = false;
    #pragma unroll
    for (int i = 0; i < 4; i++){   // 4 float4 x 32 lanes = full row ✓
        float4 v = p[lane + i*32];
        nz |= (v.x != 0.f) || (v.y != 0.f) || (v.z != 0.f) || (v.w != 0.f);
        o[lane + i*32] = make_uint2(pk2(v.x, v.y), pk2(v.z, v.w));
    }
    unsigned m = __ballot_sync(0xffffffffu, nz);
    if (lane == 0) g_valid[row] = (m != 0u);
}

// prep_w: W -> fp16. grid (DM*DM/1024, 3), 256 thr, 1 float4/thread.
__global__ void prep_w(const float* __restrict__ Wq,
                       const float* __restrict__ Wk,
                       const float* __restrict__ Wv){
    const int z = blockIdx.y;
    const float* src = (z==0) ? Wq : (z==1) ? Wk : Wv;
    int idx = blockIdx.x * 256 + threadIdx.x;
    float4 v = ((const float4*)src)[idx];
    ((uint2*)(g_wh + (size_t)z*(DM*DM/2)))[idx] = make_uint2(pk2(v.x,v.y), pk2(v.z,v.w));
}

// ---------------------------------------------------------------------------
// proj: out = relu(Q @ W^T + b), fp16 mma. Block 128x128, BK=64, 3-stage.
// Outputs: z=0 q fp32; z=1 k fp16; z=2 V^T fp16.  (R14/15-proven)
// ---------------------------------------------------------------------------
#define P_STG (128*HT_STR*2)

__global__ __launch_bounds__(256, 2) void proj_kernel(
    const float* __restrict__ bq, const float* __restrict__ bk,
    const float* __restrict__ bv)
{
    extern __shared__ unsigned smem[];
    const int z = blockIdx.z;
    const float* bias = (z==0) ? bq : (z==1) ? bk : bv;
    const unsigned* gA = g_qh;
    const unsigned* gB = g_wh + (size_t)z*(DM*DM/2);

    const int m0 = blockIdx.y * 128, n0 = blockIdx.x * 128;
    const int tid = threadIdx.x, warp = tid >> 5, lane = tid & 31;
    const int wm = warp >> 1, wn = warp & 1;
    const unsigned smb = (unsigned)__cvta_generic_to_shared(smem);

    float acc[2][8][4];
    #pragma unroll
    for (int i=0;i<2;i++)
        #pragma unroll
        for (int j=0;j<8;j++)
            #pragma unroll
            for (int r=0;r<4;r++) acc[i][j][r] = 0.f;

    auto issue = [&](int kt, int buf){
        unsigned base = smb + (unsigned)(buf*P_STG)*4u;
        #pragma unroll
        for (int t = 0; t < 4; t++){
            int idx = tid + t*256, r = idx >> 3, c = (idx & 7) * 4;
            cpasync16(base + (unsigned)(r*HT_STR + c)*4u,
                      gA + (size_t)(m0 + r)*(DM/2) + kt*32 + c);
            cpasync16(base + (unsigned)(128*HT_STR + r*HT_STR + c)*4u,
                      gB + (size_t)(n0 + r)*(DM/2) + kt*32 + c);
        }
        CP_COMMIT();
    };

    issue(0, 0); issue(1, 1);

    for (int kt = 0; kt < 8; kt++){
        if (kt < 6) CP_WAIT(1); else CP_WAIT(0);
        __syncthreads();
        if (kt + 2 < 8) issue(kt + 2, (kt + 2) % 3);

        const unsigned* As = smem + (kt % 3)*P_STG;
        const unsigned* Bs = As + 128*HT_STR;
        #pragma unroll
        for (int ks = 0; ks < 32; ks += 8){
            const int cb = ks + (lane & 3);
            unsigned a[2][4];
            #pragma unroll
            for (int mi = 0; mi < 2; mi++){
                int r0 = wm*32 + mi*16 + (lane >> 2);
                a[mi][0] = As[ r0   *HT_STR + cb];
                a[mi][1] = As[(r0+8)*HT_STR + cb];
                a[mi][2] = As[ r0   *HT_STR + cb + 4];
                a[mi][3] = As[(r0+8)*HT_STR + cb + 4];
            }
            #pragma unroll
            for (int ni = 0; ni < 8; ni++){
                int c0 = wn*64 + ni*8 + (lane >> 2);
                unsigned bf[2] = { Bs[c0*HT_STR + cb], Bs[c0*HT_STR + cb + 4] };
                mma16(acc[0][ni], a[0], bf);
                mma16(acc[1][ni], a[1], bf);
            }
        }
        __syncthreads();
    }

    #pragma unroll
    for (int mi = 0; mi < 2; mi++){
        #pragma unroll
        for (int ni = 0; ni < 8; ni++){
            int row = m0 + wm*32 + mi*16 + (lane >> 2);
            int col = n0 + wn*64 + ni*8 + (lane & 3)*2;
            float b0 = __ldg(bias + col), b1 = __ldg(bias + col + 1);
            float v00 = fmaxf(acc[mi][ni][0] + b0, 0.f), v01 = fmaxf(acc[mi][ni][1] + b1, 0.f);
            float v10 = fmaxf(acc[mi][ni][2] + b0, 0.f), v11 = fmaxf(acc[mi][ni][3] + b1, 0.f);
            if (z == 0){
                *(float2*)(g_q + (size_t)row*DM + col)     = make_float2(v00, v01);
                *(float2*)(g_q + (size_t)(row+8)*DM + col) = make_float2(v10, v11);
            } else if (z == 1){
                g_kh[(size_t)row*(DM/2) + col/2]     = pk2(v00, v01);
                g_kh[(size_t)(row+8)*(DM/2) + col/2] = pk2(v10, v11);
            } else {              // V^T fp16 [b,h][n][k=s]
                int bb2 = row >> 10, s = row & (SEQ-1);
                int hh  = col >> 6,  n = col & 63;
                size_t nb = (size_t)(bb2*NH + hh)*HD;
                g_vt[(nb + n    )*SEQ + s    ] = __float2half_rn(v00);
                g_vt[(nb + n + 1)*SEQ + s    ] = __float2half_rn(v01);
                g_vt[(nb + n    )*SEQ + s + 8] = __float2half_rn(v10);
                g_vt[(nb + n + 1)*SEQ + s + 8] = __float2half_rn(v11);
            }
        }
    }
}

// ---------------------------------------------------------------------------
// fused attention: scores + no-max softmax + weights write + P@V + residual.
// 512 threads, 16 warps 4(wm) x 4(wn), per (b, h, 128-row q-tile).
// pass 0: 3-stage K pipeline, Q frags hoisted to regs, ex2 -> rowsums.
// pass 1: 2-stage K+V, score mma split into ni-pairs (lower peak regs,
//         MUFU interleaved with HMMA), weights -> wout, P@V via FA reg trick.
// ---------------------------------------------------------------------------
__global__ __launch_bounds__(512) void fused_attn(float* __restrict__ wout){
    extern __shared__ unsigned smem[];
    unsigned* sQ   = smem;                      // 128*36
    unsigned* sK   = sQ + 128*HT_STR;           // 3 * 128*36 (pass0: 3 bufs; pass1: 2)
    unsigned* sVT  = sK + 3*KTH_U;              // 2 * 64*68
    float*    kb   = (float*)(sVT + 2*VTT_U);   // 1024
    float*    sRS2 = kb + SEQ;                  // 4*128
    float*    sRS  = sRS2 + 512;                // 128
    float*    red  = (float*)sK;                // reuse: 128*72 fp32 (fits)

    const int b = blockIdx.z, h = blockIdx.y;
    const int q0 = blockIdx.x * 128;
    const int tid = threadIdx.x, warp = tid >> 5, lane = tid & 31;
    const int wm = warp >> 2, wn = warp & 3;
    const int rowbase = b * SEQ;

    // Q tile: 128x64 fp32 -> scaled fp16. 2048 float4 = 4 x 512 ✓
    #pragma unroll
    for (int t = 0; t < 4; t++){
        int idx = tid + t*512, r = idx >> 4, c = (idx & 15) * 4;
        float4 v = *(const float4*)(g_q + (size_t)(rowbase + q0 + r)*DM + h*HD + c);
        *(uint2*)&sQ[r*HT_STR + c/2] = make_uint2(
            pk2(v.x*SCALE_L2E, v.y*SCALE_L2E), pk2(v.z*SCALE_L2E, v.w*SCALE_L2E));
    }
    for (int i = tid; i < SEQ; i += 512)
        kb[i] = g_valid[rowbase + i] ? 0.f : NEGINF;
    __syncthreads();

    const unsigned skb = (unsigned)__cvta_generic_to_shared(sK);
    const unsigned svb = (unsigned)__cvta_generic_to_shared(sVT);
    const unsigned* gK  = g_kh + (size_t)rowbase*(DM/2) + h*(HD/2);
    const unsigned* gVT = (const unsigned*)g_vt + (size_t)(b*NH + h)*HD*(SEQ/2);

    // K tile: 128 rows x 32 u32 = 1024 chunks = 2 x 512 ✓
    auto issueK = [&](int ktile, int buf){
        const unsigned base = skb + (unsigned)(buf*KTH_U)*4u;
        #pragma unroll
        for (int t = 0; t < 2; t++){
            int idx = tid + t*512, r = idx >> 3, c = (idx & 7) * 4;
            cpasync16(base + ((unsigned)(r*HT_STR + c))*4u,
                      gK + (size_t)(ktile*128 + r)*(DM/2) + c);
        }
    };
    // V^T tile: 64 rows x 64 u32 = 1024 chunks = 2 x 512 ✓
    auto issueV = [&](int ktile, int buf){
        const unsigned base = svb + (unsigned)(buf*VTT_U)*4u;
        #pragma unroll
        for (int t = 0; t < 2; t++){
            int idx = tid + t*512, r = idx >> 4, c = (idx & 15) * 4;
            cpasync16(base + ((unsigned)(r*VT_STR + c))*4u,
                      gVT + (size_t)r*(SEQ/2) + ktile*64 + c);
        }
    };

    float rsum[4] = {0.f, 0.f, 0.f, 0.f};
    float rs[4];

    // ---- pass 0: rowsums (3-stage K, Q frags in regs) ----
    {
        // hoist Q fragments: qa[ksi][mi][4], ksi = ks/8 (32 regs, pass-0 only)
        unsigned qa[4][2][4];
        #pragma unroll
        for (int ksi = 0; ksi < 4; ksi++){
            const int cb = ksi*8 + (lane & 3);
            #pragma unroll
            for (int mi = 0; mi < 2; mi++){
                int r0 = wm*32 + mi*16 + (lane >> 2);
                qa[ksi][mi][0] = sQ[ r0   *HT_STR + cb];
                qa[ksi][mi][1] = sQ[(r0+8)*HT_STR + cb];
                qa[ksi][mi][2] = sQ[ r0   *HT_STR + cb + 4];
                qa[ksi][mi][3] = sQ[(r0+8)*HT_STR + cb + 4];
            }
        }

        issueK(0, 0); CP_COMMIT();
        issueK(1, 1); CP_COMMIT();

        #pragma unroll 1
        for (int kt = 0; kt < 8; kt++){
            if (kt < 6){ issueK(kt + 2, (kt + 2) % 3); CP_COMMIT(); CP_WAIT(2); }
            else if (kt == 6) CP_WAIT(1);
            else CP_WAIT(0);
            __syncthreads();

            const unsigned* sKc = sK + (kt % 3)*KTH_U;
            float acc[2][4][4];
            #pragma unroll
            for (int i=0;i<2;i++)
                #pragma unroll
                for (int j=0;j<4;j++)
                    #pragma unroll
                    for (int r=0;r<4;r++) acc[i][j][r] = 0.f;

            #pragma unroll
            for (int ksi = 0; ksi < 4; ksi++){
                const int cb = ksi*8 + (lane & 3);
                #pragma unroll
                for (int ni = 0; ni < 4; ni++){
                    int c0 = wn*32 + ni*8 + (lane >> 2);
                    unsigned bf[2] = { sKc[c0*HT_STR + cb], sKc[c0*HT_STR + cb + 4] };
                    mma16(acc[0][ni], qa[ksi][0], bf);
                    mma16(acc[1][ni], qa[ksi][1], bf);
                }
            }
            #pragma unroll
            for (int ni = 0; ni < 4; ni++){
                const int cl = kt*128 + wn*32 + ni*8 + (lane & 3)*2;
                const float2 kb2 = *(const float2*)&kb[cl];
                rsum[0] += ex2(acc[0][ni][0] + kb2.x) + ex2(acc[0][ni][1] + kb2.y);
                rsum[1] += ex2(acc[0][ni][2] + kb2.x) + ex2(acc[0][ni][3] + kb2.y);
                rsum[2] += ex2(acc[1][ni][0] + kb2.x) + ex2(acc[1][ni][1] + kb2.y);
                rsum[3] += ex2(acc[1][ni][2] + kb2.x) + ex2(acc[1][ni][3] + kb2.y);
            }
            __syncthreads();
        }
    }

    // prefetch pass-1 tile 0 (K buf0 + V buf0) — overlaps the rs reduction
    issueK(0, 0); issueV(0, 0); CP_COMMIT();

    // reduce rowsums: quad shfl, then 4 wn warps via smem
    #pragma unroll
    for (int j = 0; j < 4; j++){
        rsum[j] += __shfl_xor_sync(0xffffffffu, rsum[j], 1);
        rsum[j] += __shfl_xor_sync(0xffffffffu, rsum[j], 2);
    }
    if ((lane & 3) == 0){
        #pragma unroll
        for (int j = 0; j < 4; j++){
            int row = wm*32 + (j>>1)*16 + (j&1)*8 + (lane>>2);
            sRS2[wn*128 + row] = rsum[j];
        }
    }
    __syncthreads();
    if (tid < 128){
        float s = sRS2[tid] + sRS2[128+tid] + sRS2[256+tid] + sRS2[384+tid];
        bool vq = g_valid[rowbase + q0 + tid] != 0;
        sRS[tid] = (vq && s > 0.f) ? (1.f / s) : 0.f;   // invalid q -> 0
    }
    __syncthreads();
    #pragma unroll
    for (int j = 0; j < 4; j++)
        rs[j] = sRS[wm*32 + (j>>1)*16 + (j&1)*8 + (lane>>2)];

    // ---- pass 1: weights + P@V (ni-pair split keeps regs under cap) ----
    float acco[2][8][4];
    #pragma unroll
    for (int i=0;i<2;i++)
        #pragma unroll
        for (int j=0;j<8;j++)
            #pragma unroll
            for (int r=0;r<4;r++) acco[i][j][r] = 0.f;

    #pragma unroll 1
    for (int kt = 0; kt < 8; kt++){
        if (kt < 7){ issueK(kt + 1, (kt + 1) & 1); issueV(kt + 1, (kt + 1) & 1);
                     CP_COMMIT(); CP_WAIT(1); }
        else CP_WAIT(0);
        __syncthreads();

        const unsigned* sKc = sK  + (kt & 1)*KTH_U;
        const unsigned* sVc = sVT + (kt & 1)*VTT_U;

        unsigned AF[2][2][4];   // [mi][ksub][4]
        #pragma unroll
        for (int nip = 0; nip < 2; nip++){
            float acc[2][2][4];
            #pragma unroll
            for (int i=0;i<2;i++)
                #pragma unroll
                for (int j=0;j<2;j++)
                    #pragma unroll
                    for (int r=0;r<4;r++) acc[i][j][r] = 0.f;

            #pragma unroll
            for (int ksi = 0; ksi < 4; ksi++){
                const int cb = ksi*8 + (lane & 3);
                unsigned a[2][4];
                #pragma unroll
                for (int mi = 0; mi < 2; mi++){
                    int r0 = wm*32 + mi*16 + (lane >> 2);
                    a[mi][0] = sQ[ r0   *HT_STR + cb];
                    a[mi][1] = sQ[(r0+8)*HT_STR + cb];
                    a[mi][2] = sQ[ r0   *HT_STR + cb + 4];
                    a[mi][3] = sQ[(r0+8)*HT_STR + cb + 4];
                }
                #pragma unroll
                for (int nio = 0; nio < 2; nio++){
                    int c0 = wn*32 + (nip*2 + nio)*8 + (lane >> 2);
                    unsigned bf[2] = { sKc[c0*HT_STR + cb], sKc[c0*HT_STR + cb + 4] };
                    mma16(acc[0][nio], a[0], bf);
                    mma16(acc[1][nio], a[1], bf);
                }
            }
            // epilogue for this ni pair
            #pragma unroll
            for (int nio = 0; nio < 2; nio++){
                const int cl = kt*128 + wn*32 + (nip*2 + nio)*8 + (lane & 3)*2;
                const float2 kb2 = *(const float2*)&kb[cl];
                float w0 = ex2(acc[0][nio][0] + kb2.x)*rs[0];
                float w1 = ex2(acc[0][nio][1] + kb2.y)*rs[0];
                float w2 = ex2(acc[0][nio][2] + kb2.x)*rs[1];
                float w3 = ex2(acc[0][nio][3] + kb2.y)*rs[1];
                float w4 = ex2(acc[1][nio][0] + kb2.x)*rs[2];
                float w5 = ex2(acc[1][nio][1] + kb2.y)*rs[2];
                float w6 = ex2(acc[1][nio][2] + kb2.x)*rs[3];
                float w7 = ex2(acc[1][nio][3] + kb2.y)*rs[3];
                size_t rg = (size_t)((b*NH + h)*SEQ + q0 + wm*32 + (lane>>2));
                *(float2*)(wout + rg*SEQ + cl)      = make_float2(w0, w1);
                *(float2*)(wout + (rg+ 8)*SEQ + cl) = make_float2(w2, w3);
                *(float2*)(wout + (rg+16)*SEQ + cl) = make_float2(w4, w5);
                *(float2*)(wout + (rg+24)*SEQ + cl) = make_float2(w6, w7);
                // C-frag -> A-frag (FA trick): ni = nip*2+nio
                AF[0][nip][nio*2    ] = pk2(w0, w1);
                AF[0][nip][nio*2 + 1] = pk2(w2, w3);
                AF[1][nip][nio*2    ] = pk2(w4, w5);
                AF[1][nip][nio*2 + 1] = pk2(w6, w7);
            }
        }

        // acc_o += P @ V^T  (warp k-slice: fp16 k = kt*128 + wn*32 + ksub*16)
        #pragma unroll
        for (int ksub = 0; ksub < 2; ksub++){
            const int cb = wn*16 + ksub*8 + (lane & 3);
            #pragma unroll
            for (int nj = 0; nj < 8; nj++){
                int c0 = nj*8 + (lane >> 2);
                unsigned bf[2] = { sVc[c0*VT_STR + cb], sVc[c0*VT_STR + cb + 4] };
                mma16(acco[0][nj], AF[0][ksub], bf);
                mma16(acco[1][nj], AF[1][ksub], bf);
            }
        }
        __syncthreads();
    }

    // ---- cross-warp acc_o reduction over wn (sequential into red) ----
    #pragma unroll 1
    for (int s = 0; s < 4; s++){
        if (wn == s){
            #pragma unroll
            for (int mi = 0; mi < 2; mi++){
                #pragma unroll
                for (int nj = 0; nj < 8; nj++){
                    int r = wm*32 + mi*16 + (lane >> 2);
                    int c = nj*8 + (lane & 3)*2;
                    if (s == 0){
                        *(float2*)&red[ r   *RED_STR + c] = make_float2(acco[mi][nj][0], acco[mi][nj][1]);
                        *(float2*)&red[(r+8)*RED_STR + c] = make_float2(acco[mi][nj][2], acco[mi][nj][3]);
                    } else {
                        float2 x0 = *(float2*)&red[ r   *RED_STR + c];
                        float2 x1 = *(float2*)&red[(r+8)*RED_STR + c];
                        *(float2*)&red[ r   *RED_STR + c] = make_float2(x0.x + acco[mi][nj][0], x0.y + acco[mi][nj][1]);
                        *(float2*)&red[(r+8)*RED_STR + c] = make_float2(x1.x + acco[mi][nj][2], x1.y + acco[mi][nj][3]);
                    }
                }
            }
        }
        __syncthreads();
    }

    // output + residual: 128x64 = 2048 float4 = 4 x 512 ✓
    #pragma unroll
    for (int t = 0; t < 4; t++){
        int idx = tid + t*512, r = idx >> 4, c = (idx & 15) * 4;
        float4 s4 = *(const float4*)&red[r*RED_STR + c];
        size_t base = (size_t)(rowbase + q0 + r)*DM + h*HD + c;
        float4 q4 = *(const float4*)(g_q + base);
        *(float4*)(g_att + base) = make_float4(s4.x+q4.x, s4.y+q4.y, s4.z+q4.z, s4.w+q4.w);
    }
}

// ---------------------------------------------------------------------------
// ln: LayerNorm + relu, one block (128 thr) per row
// ---------------------------------------------------------------------------
__global__ __launch_bounds__(128) void ln_kernel(const float* __restrict__ lnw,
                                                 const float* __restrict__ lnb,
                                                 float* __restrict__ out){
    const int row = blockIdx.x, tid = threadIdx.x;
    const float4 x = *(const float4*)(g_att + (size_t)row*DM + tid*4);
    float s  = x.x + x.y + x.z + x.w;
    float ss = fmaf(x.x, x.x, fmaf(x.y, x.y, fmaf(x.z, x.z, x.w*x.w)));
    #pragma unroll
    for (int o = 16; o > 0; o >>= 1){
        s  += __shfl_xor_sync(0xffffffffu, s,  o);
        ss += __shfl_xor_sync(0xffffffffu, ss, o);
    }
    __shared__ float red[8];
    int warp = tid >> 5, lane = tid & 31;
    if (lane == 0){ red[warp] = s; red[warp+4] = ss; }
    __syncthreads();
    s  = red[0] + red[1] + red[2] + red[3];
    ss = red[4] + red[5] + red[6] + red[7];
    float mu  = s * (1.0f/DM);
    float inv = rsqrtf(ss * (1.0f/DM) - mu*mu + 1e-5f);
    const float4 w = *(const float4*)(lnw + tid*4);
    const float4 bb = *(const float4*)(lnb + tid*4);
    float4 y;
    y.x = fmaxf((x.x - mu)*inv*w.x + bb.x, 0.f);
    y.y = fmaxf((x.y - mu)*inv*w.y + bb.y, 0.f);
    y.z = fmaxf((x.z - mu)*inv*w.z + bb.z, 0.f);
    y.w = fmaxf((x.w - mu)*inv*w.w + bb.w, 0.f);
    *(float4*)(out + (size_t)row*DM + tid*4) = y;
}

// ---------------------------------------------------------------------------
extern "C" void kernel_launch(void* const* d_in, const int* in_sizes, int n_in,
                              void* d_out, int out_size){
    const float* Q   = (const float*)d_in[0];
    const float* Wq  = (const float*)d_in[1];
    const float* bq  = (const float*)d_in[2];
    const float* Wk  = (const float*)d_in[3];
    const float* bk  = (const float*)d_in[4];
    const float* Wv  = (const float*)d_in[5];
    const float* bv  = (const float*)d_in[6];
    const float* lnw = (const float*)d_in[7];
    const float* lnb = (const float*)d_in[8];
    float* out = (float*)d_out;

    prep_q<<<NROWS/8, 256>>>(Q);
    prep_w<<<dim3(DM*DM/1024, 3), 256>>>(Wq, Wk, Wv);

    const int pj_smem = 3 * P_STG * 4;   // 110592
    cudaFuncSetAttribute(proj_kernel, cudaFuncAttributeMaxDynamicSharedMemorySize, pj_smem);
    proj_kernel<<<dim3(DM/128, NROWS/128, 3), 256, pj_smem>>>(bq, bk, bv);

    // fused smem: 128*36 + 3*128*36 + 2*64*68 u32 + (1024 + 512 + 128) fp32
    const int fa_smem = (128*HT_STR + 3*KTH_U + 2*VTT_U)*4 + (SEQ + 512 + 128)*4;  // 115200
    cudaFuncSetAttribute(fused_attn, cudaFuncAttributeMaxDynamicSharedMemorySize, fa_smem);
    fused_attn<<<dim3(SEQ/128, NH, NB), 512, fa_smem>>>(out + OUT0);

    ln_kernel<<<NROWS, 128>>>(lnw, lnb, out);
}